// round 2
// baseline (speedup 1.0000x reference)
#include <cuda_runtime.h>
#include <cstdint>
#include <cstddef>

// Problem constants
#define T_  4
#define B_  1024
#define S_  64          // WH*WW
#define C_  256
#define NQ  4           // output-channel quarters (64 j each)
#define NBY 37          // token-group CTAs per quarter (4*37=148 = 1 wave)
#define Y_ELEMS (67108864LL)   // T*B*S*C

// ---------------- device scratch (no allocations allowed) ----------------
__device__ float4   g_Wpack[NQ * 256 * 32];          // packed (Wq,Wk) quarters, 512 KB
__device__ float    g_WpT[C_ * C_];                  // Wp transposed, 256 KB
__device__ uint32_t g_masks[(size_t)B_ * S_ * T_ * 8];   // xs spike bitmasks, 8 MB
__device__ uint32_t g_kbits[(size_t)T_ * B_ * S_ * 8];   // k spike bits, 8 MB
__device__ uint8_t  g_att[(size_t)T_ * B_ * 8 * S_];     // att spikes, 2 MB

// ---------------- prep: pack Wq/Wk into per-quarter lane-major float4 ----------------
// g_Wpack[jq*8192 + c*32 + lane] = (Wq[j0][c], Wk[j0][c], Wq[j1][c], Wk[j1][c])
// where j0 = jq*64+lane, j1 = j0+32.
__global__ void prep_pack(const float* __restrict__ Wq, const float* __restrict__ Wk) {
    int idx = blockIdx.x * 256 + threadIdx.x;   // 0..32767
    int lane = idx & 31, c = (idx >> 5) & 255, jq = idx >> 13;
    int j0 = jq * 64 + lane, j1 = j0 + 32;
    g_Wpack[idx] = make_float4(Wq[j0 * C_ + c], Wk[j0 * C_ + c],
                               Wq[j1 * C_ + c], Wk[j1 * C_ + c]);
}

__global__ void prep_wp(const float* __restrict__ Wp) {
    __shared__ float t[32][33];
    int tx = threadIdx.x, ty = threadIdx.y;
    int j0 = blockIdx.y * 32, c0 = blockIdx.x * 32;
    t[ty][tx] = Wp[(j0 + ty) * C_ + c0 + tx];
    __syncthreads();
    g_WpT[(c0 + ty) * C_ + j0 + tx] = t[tx][ty];
}

// ---------------- K1: LIF on raw input -> packed spike masks ----------------
__global__ void __launch_bounds__(256) lif_mask(const float* __restrict__ x) {
    int s = blockIdx.x, b = blockIdx.y;
    int c = threadIdx.x, warp = c >> 5, lane = c & 31;
    float v = 0.0f;
    const float* xp = x + (size_t)b * 16384 + (size_t)s * 256 + c;
    uint32_t base = (uint32_t)(b * 64 + s) * 32;
#pragma unroll
    for (int t = 0; t < T_; t++) {
        float xv = __ldg(xp + (size_t)t * 16777216);
        v += (xv - v) * 0.5f;
        bool sp = (v - 1.0f) >= 0.0f;
        uint32_t m = __ballot_sync(0xffffffffu, sp);
        if (sp) v = 0.0f;
        if (lane == 0) g_masks[base + t * 8 + warp] = m;
    }
}

// ---------------- K2: sparse Q/K matvec from SMEM-resident weight quarter ----------------
// CTA = (jq quarter, token group). Each warp owns a token at a time, covers all
// 64 j of the quarter (lane -> j_local lane and lane+32) with one LDS.128/active-c.
extern __shared__ float4 sW[];  // 8192 float4 = 128 KB

__global__ void __launch_bounds__(256) qk_kernel(const float* __restrict__ pos) {
    const int jq  = blockIdx.x;
    const int grp = blockIdx.y;
    const int tid = threadIdx.x, warp = tid >> 5, lane = tid & 31;

    // Stage this quarter's weight slice into SMEM once.
    const float4* src = g_Wpack + jq * 8192;
    for (int i = tid; i < 8192; i += 256) sW[i] = src[i];
    __syncthreads();

    const int tok0 = (grp * 65536) / NBY;
    const int tok1 = ((grp + 1) * 65536) / NBY;
    const int h0 = 2 * jq;
    const int jbase = jq * 64;

    for (int i = tok0 + warp; i < tok1; i += 8) {
        const int b = i >> 6, s = i & 63;
        const uint32_t* mrow = g_masks + (size_t)i * 32;
        float vq0 = 0.f, vq1 = 0.f, vk0 = 0.f, vk1 = 0.f, va0 = 0.f, va1 = 0.f;
#pragma unroll
        for (int t = 0; t < T_; t++) {
            float aq0 = 0.f, aq1 = 0.f;
            float ak0 = __ldg(pos + (t * 64 + s) * 256 + jbase + lane);
            float ak1 = __ldg(pos + (t * 64 + s) * 256 + jbase + 32 + lane);
#pragma unroll
            for (int w = 0; w < 8; w++) {
                uint32_t m = mrow[t * 8 + w];   // uniform across warp
                while (m) {
                    int c = (w << 5) + __ffs(m) - 1;
                    m &= m - 1;
                    float4 wv = sW[c * 32 + lane];
                    aq0 += wv.x; ak0 += wv.y; aq1 += wv.z; ak1 += wv.w;
                }
            }
            // LIF updates (exact same form/order as reference)
            vq0 += (aq0 - vq0) * 0.5f; bool sq0 = (vq0 - 1.f) >= 0.f; if (sq0) vq0 = 0.f;
            vq1 += (aq1 - vq1) * 0.5f; bool sq1 = (vq1 - 1.f) >= 0.f; if (sq1) vq1 = 0.f;
            vk0 += (ak0 - vk0) * 0.5f; bool sk0 = (vk0 - 1.f) >= 0.f; if (sk0) vk0 = 0.f;
            vk1 += (ak1 - vk1) * 0.5f; bool sk1 = (vk1 - 1.f) >= 0.f; if (sk1) vk1 = 0.f;

            uint32_t kb0 = __ballot_sync(0xffffffffu, sk0);
            uint32_t kb1 = __ballot_sync(0xffffffffu, sk1);
            int cnt0 = __popc(__ballot_sync(0xffffffffu, sq0));
            int cnt1 = __popc(__ballot_sync(0xffffffffu, sq1));
            va0 += ((float)cnt0 - va0) * 0.5f; bool sa0 = (va0 - 1.f) >= 0.f; if (sa0) va0 = 0.f;
            va1 += ((float)cnt1 - va1) * 0.5f; bool sa1 = (va1 - 1.f) >= 0.f; if (sa1) va1 = 0.f;

            if (lane == 0) {
                size_t kbase = (((size_t)t * B_ + b) * S_ + s) * 8;
                g_kbits[kbase + h0]     = kb0;
                g_kbits[kbase + h0 + 1] = kb1;
                size_t abase = ((size_t)t * B_ + b) * 8;
                g_att[(abase + h0) * 64 + s]     = sa0 ? 1u : 0u;
                g_att[(abase + h0 + 1) * 64 + s] = sa1 ? 1u : 0u;
            }
        }
    }
}

// ---------------- K3: gather x2 bits, sparse Wp matvec + bias, write y; zero attn_out ----------------
__global__ void __launch_bounds__(256) kernelB(const float* __restrict__ bp,
                                               float* __restrict__ out, int write_zero) {
    const int s = blockIdx.x;
    const int b = blockIdx.y;
    const int j = threadIdx.x;
    const int h = j >> 5, d = j & 31;
    const int wh = s >> 3, ww = s & 7;

    const int t_k = b >> 8;
    const int b_k = (b & 255) * 4 + (h >> 1);

    __shared__ uint32_t x2m[T_][8];

#pragma unroll
    for (int t = 0; t < T_; t++) {
        int s_k = ((h & 1) << 5) + t * 8 + wh;
        uint32_t kw = g_kbits[(((size_t)t_k * B_ + b_k) * S_ + s_k) * 8 + ww];
        uint8_t ab = g_att[(((size_t)t_k * B_ + b_k) * 8 + ((h & 1) * 4 + t)) * S_ + s];
        bool x2 = (((kw >> d) & 1u) != 0u) && (ab != 0u);
        uint32_t m = __ballot_sync(0xffffffffu, x2);
        if (d == 0) x2m[t][h] = m;
    }
    __syncthreads();

    const float bias = __ldg(bp + j);
#pragma unroll
    for (int t = 0; t < T_; t++) {
        float acc = bias;
#pragma unroll
        for (int w = 0; w < 8; w++) {
            uint32_t m = x2m[t][w];
            while (m) {
                int c = (w << 5) + __ffs(m) - 1;
                m &= m - 1;
                acc += g_WpT[c * C_ + j];
            }
        }
        size_t off = (((size_t)t * B_ + b) * S_ + s) * 256 + j;
        out[off] = acc;
        // attn_out = lif(x2) is identically zero: x2 in {0,1}, v <- (v+x)/2 < 1 always
        // (exact dyadic fp32 in both our math and the reference).
        if (write_zero) out[Y_ELEMS + off] = 0.0f;
    }
}

__global__ void zfill_tail(float* __restrict__ p, size_t n) {
    size_t i = (size_t)blockIdx.x * blockDim.x + threadIdx.x;
    if (i < n) p[i] = 0.f;
}

extern "C" void kernel_launch(void* const* d_in, const int* in_sizes, int n_in,
                              void* d_out, int out_size) {
    const float* x   = (const float*)d_in[0];
    const float* Wq  = (const float*)d_in[1];
    const float* Wk  = (const float*)d_in[2];
    const float* Wp  = (const float*)d_in[3];
    const float* bp  = (const float*)d_in[4];
    const float* pos = (const float*)d_in[5];
    float* out = (float*)d_out;

    // Allow 128 KB dynamic SMEM for the weight-resident kernel (idempotent).
    cudaFuncSetAttribute(qk_kernel, cudaFuncAttributeMaxDynamicSharedMemorySize, 131072);

    prep_pack<<<128, 256>>>(Wq, Wk);
    prep_wp<<<dim3(8, 8), dim3(32, 32)>>>(Wp);
    lif_mask<<<dim3(64, 1024), 256>>>(x);
    qk_kernel<<<dim3(NQ, NBY), 256, 131072>>>(pos);

    int write_zero = ((long long)out_size >= 2 * Y_ELEMS) ? 1 : 0;
    kernelB<<<dim3(64, 1024), 256>>>(bp, out, write_zero);

    long long extra = (long long)out_size - (write_zero ? 2 * Y_ELEMS : Y_ELEMS);
    if (extra > 0) {
        long long base = write_zero ? 2 * Y_ELEMS : Y_ELEMS;
        int blocks = (int)((extra + 255) / 256);
        zfill_tail<<<blocks, 256>>>(out + base, (size_t)extra);
    }
}

// round 3
// speedup vs baseline: 1.2921x; 1.2921x over previous
#include <cuda_runtime.h>
#include <cstdint>
#include <cstddef>

// Problem constants
#define T_  4
#define B_  1024
#define S_  64          // WH*WW
#define C_  256
#define NSL 8           // j-slices (32 j each) == heads
#define NGR 55          // token groups: 8*55 = 440 CTAs ~= one wave @ 3 CTA/SM
#define Y_ELEMS (67108864LL)   // T*B*S*C

// ---------------- device scratch (statics only; no runtime allocation) ----------------
__device__ float2   g_Wpack2[NSL * 256 * 32];            // (Wq,Wk) per slice, 512 KB
__device__ float    g_WpT[C_ * C_];                      // Wp transposed, 256 KB
__device__ uint8_t  g_idx[(size_t)B_ * S_ * T_ * 256];   // active-channel lists, 64 MB
__device__ uint32_t g_cnt[(size_t)B_ * S_];              // 4 packed uint8 counts per token
__device__ uint32_t g_kbits[(size_t)T_ * B_ * S_ * 8];   // k spike bits, 8 MB
__device__ uint8_t  g_att[(size_t)T_ * B_ * 8 * S_];     // att spikes, 2 MB

// ---------------- prep: pack Wq/Wk into per-slice lane-major float2 ----------------
// g_Wpack2[sl*8192 + c*32 + lane] = (Wq[j][c], Wk[j][c]),  j = sl*32 + lane
__global__ void prep_pack(const float* __restrict__ Wq, const float* __restrict__ Wk) {
    int idx = blockIdx.x * 256 + threadIdx.x;   // 0..65535
    int lane = idx & 31, c = (idx >> 5) & 255, sl = idx >> 13;
    int j = sl * 32 + lane;
    g_Wpack2[idx] = make_float2(Wq[j * C_ + c], Wk[j * C_ + c]);
}

__global__ void prep_wp(const float* __restrict__ Wp) {
    __shared__ float t[32][33];
    int tx = threadIdx.x, ty = threadIdx.y;
    int j0 = blockIdx.y * 32, c0 = blockIdx.x * 32;
    t[ty][tx] = Wp[(j0 + ty) * C_ + c0 + tx];
    __syncthreads();
    g_WpT[(c0 + ty) * C_ + j0 + tx] = t[tx][ty];
}

// ---------------- K1: LIF on raw input -> compacted active-channel index lists ----------------
__global__ void __launch_bounds__(256) lif_mask(const float* __restrict__ x) {
    const int s = blockIdx.x, b = blockIdx.y;
    const int c = threadIdx.x, warp = c >> 5, lane = c & 31;
    const int tok = b * 64 + s;

    __shared__ uint32_t smask[T_][8];
    bool spv[T_];

    float v = 0.0f;
    const float* xp = x + (size_t)b * 16384 + (size_t)s * 256 + c;
#pragma unroll
    for (int t = 0; t < T_; t++) {
        float xv = __ldg(xp + (size_t)t * 16777216);
        v += (xv - v) * 0.5f;
        bool sp = (v - 1.0f) >= 0.0f;
        spv[t] = sp;
        if (sp) v = 0.0f;
        uint32_t m = __ballot_sync(0xffffffffu, sp);
        if (lane == 0) smask[t][warp] = m;
    }
    __syncthreads();

#pragma unroll
    for (int t = 0; t < T_; t++) {
        uint32_t m = smask[t][warp];
        int base = 0;
#pragma unroll
        for (int w = 0; w < 8; w++)
            if (w < warp) base += __popc(smask[t][w]);
        if (spv[t]) {
            int pos = base + __popc(m & ((1u << lane) - 1u));
            g_idx[(((size_t)tok * T_) + t) * 256 + pos] = (uint8_t)c;
        }
    }

    if (c == 0) {
        uint32_t pack = 0;
#pragma unroll
        for (int t = 0; t < T_; t++) {
            int tot = 0;
#pragma unroll
            for (int w = 0; w < 8; w++) tot += __popc(smask[t][w]);
            pack |= (uint32_t)tot << (t * 8);
        }
        g_cnt[tok] = pack;
    }
}

// ---------------- K2: sparse Q/K matvec from SMEM-resident 32-j weight slice ----------------
// CTA = (slice sl == head, token group). 64KB SMEM -> 3 CTAs/SM. Counted,
// pipelineable inner loop over precompacted channel indices.
extern __shared__ float2 sW2[];  // 8192 float2 = 64 KB

__global__ void __launch_bounds__(256) qk_kernel(const float* __restrict__ pos) {
    const int sl  = blockIdx.x;          // slice == head
    const int grp = blockIdx.y;
    const int tid = threadIdx.x, warp = tid >> 5, lane = tid & 31;

    // Stage this slice's weights (float4 vectorized).
    {
        const float4* src = (const float4*)(g_Wpack2 + sl * 8192);
        float4* dst = (float4*)sW2;
        for (int i = tid; i < 4096; i += 256) dst[i] = src[i];
    }
    __syncthreads();

    const int tok0 = (grp * 65536) / NGR;
    const int tok1 = ((grp + 1) * 65536) / NGR;
    const int jcol = sl * 32 + lane;

    for (int i = tok0 + warp; i < tok1; i += 8) {
        const int b = i >> 6, s = i & 63;
        const uint32_t cpack = __ldg(g_cnt + i);           // warp-uniform
        const uint8_t* ib = g_idx + (size_t)i * (T_ * 256);

        float vq = 0.f, vk = 0.f, va = 0.f;
#pragma unroll
        for (int t = 0; t < T_; t++) {
            const int cnt = (cpack >> (t * 8)) & 255;
            float aq = 0.f;
            float ak = __ldg(pos + (t * 64 + s) * 256 + jcol);
            const uint8_t* ip = ib + t * 256;

            for (int jj = 0; jj < cnt; jj += 4) {
                uint32_t w = __ldg((const uint32_t*)(ip + jj));  // uniform, 4B-aligned
                int rem = cnt - jj;
                {
                    int c0 = w & 255;
                    float2 wv = sW2[c0 * 32 + lane];
                    aq += wv.x; ak += wv.y;
                }
                if (rem > 1) {
                    int c1 = (w >> 8) & 255;
                    float2 wv = sW2[c1 * 32 + lane];
                    aq += wv.x; ak += wv.y;
                }
                if (rem > 2) {
                    int c2 = (w >> 16) & 255;
                    float2 wv = sW2[c2 * 32 + lane];
                    aq += wv.x; ak += wv.y;
                }
                if (rem > 3) {
                    int c3 = (w >> 24) & 255;
                    float2 wv = sW2[c3 * 32 + lane];
                    aq += wv.x; ak += wv.y;
                }
            }

            // LIF (exact same arithmetic/order as reference)
            vq += (aq - vq) * 0.5f; bool sq = (vq - 1.f) >= 0.f; if (sq) vq = 0.f;
            vk += (ak - vk) * 0.5f; bool sk = (vk - 1.f) >= 0.f; if (sk) vk = 0.f;

            uint32_t kb = __ballot_sync(0xffffffffu, sk);
            int cq = __popc(__ballot_sync(0xffffffffu, sq));
            va += ((float)cq - va) * 0.5f; bool sa = (va - 1.f) >= 0.f; if (sa) va = 0.f;

            if (lane == 0) {
                g_kbits[(((size_t)t * B_ + b) * S_ + s) * 8 + sl] = kb;
                g_att[(((size_t)t * B_ + b) * 8 + sl) * S_ + s] = sa ? 1u : 0u;
            }
        }
    }
}

// ---------------- K3: gather x2 bits, sparse Wp matvec + bias, write y; zero attn_out ----------------
__global__ void __launch_bounds__(256) kernelB(const float* __restrict__ bp,
                                               float* __restrict__ out, int write_zero) {
    const int s = blockIdx.x;
    const int b = blockIdx.y;
    const int j = threadIdx.x;
    const int h = j >> 5, d = j & 31;
    const int wh = s >> 3, ww = s & 7;

    const int t_k = b >> 8;
    const int b_k = (b & 255) * 4 + (h >> 1);

    __shared__ uint32_t x2m[T_][8];

#pragma unroll
    for (int t = 0; t < T_; t++) {
        int s_k = ((h & 1) << 5) + t * 8 + wh;
        uint32_t kw = g_kbits[(((size_t)t_k * B_ + b_k) * S_ + s_k) * 8 + ww];
        uint8_t ab = g_att[(((size_t)t_k * B_ + b_k) * 8 + ((h & 1) * 4 + t)) * S_ + s];
        bool x2 = (((kw >> d) & 1u) != 0u) && (ab != 0u);
        uint32_t m = __ballot_sync(0xffffffffu, x2);
        if (d == 0) x2m[t][h] = m;
    }
    __syncthreads();

    const float bias = __ldg(bp + j);
#pragma unroll
    for (int t = 0; t < T_; t++) {
        float acc = bias;
#pragma unroll
        for (int w = 0; w < 8; w++) {
            uint32_t m = x2m[t][w];
            while (m) {
                int c = (w << 5) + __ffs(m) - 1;
                m &= m - 1;
                acc += g_WpT[c * C_ + j];
            }
        }
        size_t off = (((size_t)t * B_ + b) * S_ + s) * 256 + j;
        out[off] = acc;
        // attn_out = lif(x2) is identically zero: x2 in {0,1}, v <- (v+x)/2 < 1 always
        // (exact dyadic fp32 in both our math and the reference).
        if (write_zero) out[Y_ELEMS + off] = 0.0f;
    }
}

__global__ void zfill_tail(float* __restrict__ p, size_t n) {
    size_t i = (size_t)blockIdx.x * blockDim.x + threadIdx.x;
    if (i < n) p[i] = 0.f;
}

extern "C" void kernel_launch(void* const* d_in, const int* in_sizes, int n_in,
                              void* d_out, int out_size) {
    const float* x   = (const float*)d_in[0];
    const float* Wq  = (const float*)d_in[1];
    const float* Wk  = (const float*)d_in[2];
    const float* Wp  = (const float*)d_in[3];
    const float* bp  = (const float*)d_in[4];
    const float* pos = (const float*)d_in[5];
    float* out = (float*)d_out;

    cudaFuncSetAttribute(qk_kernel, cudaFuncAttributeMaxDynamicSharedMemorySize, 65536);

    prep_pack<<<256, 256>>>(Wq, Wk);
    prep_wp<<<dim3(8, 8), dim3(32, 32)>>>(Wp);
    lif_mask<<<dim3(64, 1024), 256>>>(x);
    qk_kernel<<<dim3(NSL, NGR), 256, 65536>>>(pos);

    int write_zero = ((long long)out_size >= 2 * Y_ELEMS) ? 1 : 0;
    kernelB<<<dim3(64, 1024), 256>>>(bp, out, write_zero);

    long long extra = (long long)out_size - (write_zero ? 2 * Y_ELEMS : Y_ELEMS);
    if (extra > 0) {
        long long base = write_zero ? 2 * Y_ELEMS : Y_ELEMS;
        int blocks = (int)((extra + 255) / 256);
        zfill_tail<<<blocks, 256>>>(out + base, (size_t)extra);
    }
}

// round 4
// speedup vs baseline: 1.5631x; 1.2097x over previous
#include <cuda_runtime.h>
#include <cstdint>
#include <cstddef>

// Problem constants
#define T_  4
#define B_  1024
#define S_  64          // WH*WW
#define C_  256
#define NSL 8           // j-slices (32 j each) == heads
#define NGR 55          // 8*55 = 440 CTAs ~= one wave @ 3 CTA/SM
#define QKTHREADS 512
#define IDXSTRIDE 272   // uint16 slots per (token,t); 272*2=544B, 16B aligned
#define Y_ELEMS (67108864LL)   // T*B*S*C

// packed fp32x2 helpers (sm_103a)
#define ADD_F32X2(out, a, b) \
    asm("add.rn.f32x2 %0, %1, %2;" : "=l"(out) : "l"(a), "l"(b))
#define PACK_F32X2(out, lo, hi) \
    asm("mov.b64 %0, {%1, %2};" : "=l"(out) : "r"(lo), "r"(hi))
#define UNPACK_F32X2(lo, hi, in) \
    asm("mov.b64 {%0, %1}, %2;" : "=r"(lo), "=r"(hi) : "l"(in))

// ---------------- device scratch (statics only) ----------------
__device__ float2   g_Wpack2[NSL * 256 * 32];            // (Wq,Wk) per slice, 512 KB
__device__ float    g_WpT[C_ * C_];                      // Wp transposed, 256 KB
__device__ unsigned short g_idx16[(size_t)B_ * S_ * T_ * IDXSTRIDE]; // ~143 MB
__device__ uint32_t g_cnt[(size_t)B_ * S_];              // 4 packed uint8 counts / token
__device__ uint32_t g_kbits[(size_t)T_ * B_ * S_ * 8];   // k spike bits, 8 MB
__device__ uint8_t  g_att[(size_t)T_ * B_ * 8 * S_];     // att spikes, 2 MB

// ---------------- prep: pack Wq/Wk per-slice lane-major float2 ----------------
__global__ void prep_pack(const float* __restrict__ Wq, const float* __restrict__ Wk) {
    int idx = blockIdx.x * 256 + threadIdx.x;   // 0..65535
    int lane = idx & 31, c = (idx >> 5) & 255, sl = idx >> 13;
    int j = sl * 32 + lane;
    g_Wpack2[idx] = make_float2(Wq[j * C_ + c], Wk[j * C_ + c]);
}

__global__ void prep_wp(const float* __restrict__ Wp) {
    __shared__ float t[32][33];
    int tx = threadIdx.x, ty = threadIdx.y;
    int j0 = blockIdx.y * 32, c0 = blockIdx.x * 32;
    t[ty][tx] = Wp[(j0 + ty) * C_ + c0 + tx];
    __syncthreads();
    g_WpT[(c0 + ty) * C_ + j0 + tx] = t[tx][ty];
}

// ---------------- K1: LIF on raw input -> compacted uint16 channel lists ----------------
__global__ void __launch_bounds__(256) lif_mask(const float* __restrict__ x) {
    const int s = blockIdx.x, b = blockIdx.y;
    const int c = threadIdx.x, warp = c >> 5, lane = c & 31;
    const int tok = b * 64 + s;

    __shared__ uint32_t smask[T_][8];
    bool spv[T_];

    float v = 0.0f;
    const float* xp = x + (size_t)b * 16384 + (size_t)s * 256 + c;
#pragma unroll
    for (int t = 0; t < T_; t++) {
        float xv = __ldg(xp + (size_t)t * 16777216);
        v += (xv - v) * 0.5f;
        bool sp = (v - 1.0f) >= 0.0f;
        spv[t] = sp;
        if (sp) v = 0.0f;
        uint32_t m = __ballot_sync(0xffffffffu, sp);
        if (lane == 0) smask[t][warp] = m;
    }
    __syncthreads();

    unsigned short* ib = g_idx16 + (size_t)tok * (T_ * IDXSTRIDE);

#pragma unroll
    for (int t = 0; t < T_; t++) {
        uint32_t m = smask[t][warp];
        int base = 0;
#pragma unroll
        for (int w = 0; w < 8; w++)
            if (w < warp) base += __popc(smask[t][w]);
        if (spv[t]) {
            int pos = base + __popc(m & ((1u << lane) - 1u));
            ib[t * IDXSTRIDE + pos] = (unsigned short)c;
        }
    }

    // pad each list to a multiple of 4 with sentinel 256 (zero weight row)
    if (c < T_) {
        int t = c;
        int tot = 0;
#pragma unroll
        for (int w = 0; w < 8; w++) tot += __popc(smask[t][w]);
        int padded = (tot + 3) & ~3;
        for (int p = tot; p < padded; p++) ib[t * IDXSTRIDE + p] = 256;
    }
    if (c == 0) {
        uint32_t pack = 0;
#pragma unroll
        for (int t = 0; t < T_; t++) {
            int tot = 0;
#pragma unroll
            for (int w = 0; w < 8; w++) tot += __popc(smask[t][w]);
            pack |= (uint32_t)tot << (t * 8);   // counts < 256 in practice
        }
        g_cnt[tok] = pack;
    }
}

// ---------------- K2: sparse Q/K matvec, SMEM-resident 32-j slice + zero row ----------------
extern __shared__ float2 sW2[];  // 257*32 float2 = 65792 B (row 256 = zeros)

__global__ void __launch_bounds__(QKTHREADS) qk_kernel(const float* __restrict__ pos) {
    const int sl  = blockIdx.x;          // slice == head
    const int grp = blockIdx.y;
    const int tid = threadIdx.x, warp = tid >> 5, lane = tid & 31;

    // Stage weights (float4 vectorized) + zero sentinel row.
    {
        const float4* src = (const float4*)(g_Wpack2 + sl * 8192);
        float4* dst = (float4*)sW2;
        for (int i = tid; i < 4096; i += QKTHREADS) dst[i] = src[i];
        if (tid < 32) sW2[8192 + tid] = make_float2(0.f, 0.f);
    }
    __syncthreads();

    const int tok0 = (grp * 65536) / NGR;
    const int tok1 = ((grp + 1) * 65536) / NGR;
    const int jcol = sl * 32 + lane;
    const unsigned long long laneoff =
        (unsigned long long)(uintptr_t)(sW2 + lane);

    for (int i = tok0 + warp; i < tok1; i += (QKTHREADS / 32)) {
        const int b = i >> 6, s = i & 63;
        const uint32_t cpack = __ldg(g_cnt + i);           // warp-uniform
        const unsigned short* ib = g_idx16 + (size_t)i * (T_ * IDXSTRIDE);

        float vq = 0.f, vk = 0.f, va = 0.f;
#pragma unroll
        for (int t = 0; t < T_; t++) {
            const int cnt = (cpack >> (t * 8)) & 255;
            const int ng = (cnt + 3) >> 2;

            unsigned long long acc;
            {
                float pv = __ldg(pos + (t * 64 + s) * 256 + jcol);
                PACK_F32X2(acc, __float_as_uint(0.0f), __float_as_uint(pv));
            }

            const uint2* gp = (const uint2*)(ib + t * IDXSTRIDE);
            for (int g = 0; g < ng; g++) {
                uint2 w = __ldg(gp + g);                   // 4 padded indices
                int c0 = w.x & 0xFFFF, c1 = w.x >> 16;
                int c2 = w.y & 0xFFFF, c3 = w.y >> 16;
                unsigned long long w0 = *(const unsigned long long*)(sW2 + c0 * 32 + lane);
                ADD_F32X2(acc, acc, w0);
                unsigned long long w1 = *(const unsigned long long*)(sW2 + c1 * 32 + lane);
                ADD_F32X2(acc, acc, w1);
                unsigned long long w2 = *(const unsigned long long*)(sW2 + c2 * 32 + lane);
                ADD_F32X2(acc, acc, w2);
                unsigned long long w3 = *(const unsigned long long*)(sW2 + c3 * 32 + lane);
                ADD_F32X2(acc, acc, w3);
            }

            uint32_t aqb, akb;
            UNPACK_F32X2(aqb, akb, acc);
            float aq = __uint_as_float(aqb), ak = __uint_as_float(akb);

            // LIF (exact same arithmetic/order as reference)
            vq += (aq - vq) * 0.5f; bool sq = (vq - 1.f) >= 0.f; if (sq) vq = 0.f;
            vk += (ak - vk) * 0.5f; bool sk = (vk - 1.f) >= 0.f; if (sk) vk = 0.f;

            uint32_t kb = __ballot_sync(0xffffffffu, sk);
            int cq = __popc(__ballot_sync(0xffffffffu, sq));
            va += ((float)cq - va) * 0.5f; bool sa = (va - 1.f) >= 0.f; if (sa) va = 0.f;

            if (lane == 0) {
                g_kbits[(((size_t)t * B_ + b) * S_ + s) * 8 + sl] = kb;
                g_att[(((size_t)t * B_ + b) * 8 + sl) * S_ + s] = sa ? 1u : 0u;
            }
        }
    }
    (void)laneoff;
}

// ---------------- K3: gather x2 bits, sparse Wp matvec + bias, write y (+ zero attn_out) ----------------
__global__ void __launch_bounds__(256) kernelB(const float* __restrict__ bp,
                                               float* __restrict__ out, int write_zero) {
    const int s = blockIdx.x;
    const int b = blockIdx.y;
    const int j = threadIdx.x;
    const int h = j >> 5, d = j & 31;
    const int wh = s >> 3, ww = s & 7;

    const int t_k = b >> 8;
    const int b_k = (b & 255) * 4 + (h >> 1);

    __shared__ uint32_t x2m[T_][8];

#pragma unroll
    for (int t = 0; t < T_; t++) {
        int s_k = ((h & 1) << 5) + t * 8 + wh;
        uint32_t kw = g_kbits[(((size_t)t_k * B_ + b_k) * S_ + s_k) * 8 + ww];
        uint8_t ab = g_att[(((size_t)t_k * B_ + b_k) * 8 + ((h & 1) * 4 + t)) * S_ + s];
        bool x2 = (((kw >> d) & 1u) != 0u) && (ab != 0u);
        uint32_t m = __ballot_sync(0xffffffffu, x2);
        if (d == 0) x2m[t][h] = m;
    }
    __syncthreads();

    const float bias = __ldg(bp + j);
#pragma unroll
    for (int t = 0; t < T_; t++) {
        float acc = bias;
#pragma unroll
        for (int w = 0; w < 8; w++) {
            uint32_t m = x2m[t][w];
            while (m) {
                int c = (w << 5) + __ffs(m) - 1;
                m &= m - 1;
                acc += g_WpT[c * C_ + j];
            }
        }
        size_t off = (((size_t)t * B_ + b) * S_ + s) * 256 + j;
        out[off] = acc;
        // attn_out = lif(x2) is identically zero: x2 in {0,1}, v <- (v+x)/2 < 1 always.
        if (write_zero) out[Y_ELEMS + off] = 0.0f;
    }
}

__global__ void zfill_tail(float* __restrict__ p, size_t n) {
    size_t i = (size_t)blockIdx.x * blockDim.x + threadIdx.x;
    if (i < n) p[i] = 0.f;
}

extern "C" void kernel_launch(void* const* d_in, const int* in_sizes, int n_in,
                              void* d_out, int out_size) {
    const float* x   = (const float*)d_in[0];
    const float* Wq  = (const float*)d_in[1];
    const float* Wk  = (const float*)d_in[2];
    const float* Wp  = (const float*)d_in[3];
    const float* bp  = (const float*)d_in[4];
    const float* pos = (const float*)d_in[5];
    float* out = (float*)d_out;

    cudaFuncSetAttribute(qk_kernel, cudaFuncAttributeMaxDynamicSharedMemorySize, 65792);

    prep_pack<<<256, 256>>>(Wq, Wk);
    prep_wp<<<dim3(8, 8), dim3(32, 32)>>>(Wp);
    lif_mask<<<dim3(64, 1024), 256>>>(x);
    qk_kernel<<<dim3(NSL, NGR), QKTHREADS, 65792>>>(pos);

    int write_zero = ((long long)out_size >= 2 * Y_ELEMS) ? 1 : 0;
    kernelB<<<dim3(64, 1024), 256>>>(bp, out, write_zero);

    long long extra = (long long)out_size - (write_zero ? 2 * Y_ELEMS : Y_ELEMS);
    if (extra > 0) {
        long long base = write_zero ? 2 * Y_ELEMS : Y_ELEMS;
        int blocks = (int)((extra + 255) / 256);
        zfill_tail<<<blocks, 256>>>(out + base, (size_t)extra);
    }
}

// round 5
// speedup vs baseline: 1.8701x; 1.1964x over previous
#include <cuda_runtime.h>
#include <cstdint>
#include <cstddef>

// Problem constants
#define T_  4
#define B_  1024
#define S_  64          // WH*WW
#define C_  256
#define NPAIR 4         // head pairs (64 j each)
#define NGR 37          // 4*37 = 148 CTAs = one wave @ 1 CTA/SM
#define QKTHREADS 1024
#define IDXSTRIDE 272   // uint32 slots per (token,t); 1088B, 16B aligned
#define Y_ELEMS (67108864LL)   // T*B*S*C

// packed fp32x2 helpers (sm_103a)
#define ADD_F32X2(out, a, b) \
    asm("add.rn.f32x2 %0, %1, %2;" : "=l"(out) : "l"(a), "l"(b))
#define PACK_F32X2(out, lo, hi) \
    asm("mov.b64 %0, {%1, %2};" : "=l"(out) : "r"(lo), "r"(hi))
#define UNPACK_F32X2(lo, hi, in) \
    asm("mov.b64 {%0, %1}, %2;" : "=r"(lo), "=r"(hi) : "l"(in))

// ---------------- device scratch (statics only) ----------------
__device__ float4   g_Wpack4[NPAIR * 256 * 32];          // per-pair weights, 512 KB
__device__ float    g_WpT[C_ * C_];                      // Wp transposed, 256 KB
__device__ uint32_t g_off[(size_t)B_ * S_ * T_ * IDXSTRIDE]; // prescaled offsets, ~285 MB
__device__ uint32_t g_cnt[(size_t)B_ * S_];              // 4 packed group-counts / token
__device__ uint32_t g_kbits[(size_t)T_ * B_ * S_ * 8];   // k spike bits, 8 MB
__device__ uint8_t  g_att[(size_t)T_ * B_ * 8 * S_];     // att spikes, 2 MB

// ---------------- prep: pack Wq/Wk per-pair lane-major float4 ----------------
// g_Wpack4[p*8192 + c*32 + l] = (Wq[j0][c], Wk[j0][c], Wq[j1][c], Wk[j1][c])
// j0 = 64p + l (head 2p), j1 = j0 + 32 (head 2p+1)
__global__ void prep_pack(const float* __restrict__ Wq, const float* __restrict__ Wk) {
    int idx = blockIdx.x * 256 + threadIdx.x;   // 0..32767
    int lane = idx & 31, c = (idx >> 5) & 255, p = idx >> 13;
    int j0 = p * 64 + lane, j1 = j0 + 32;
    g_Wpack4[idx] = make_float4(__ldg(Wq + j0 * C_ + c), __ldg(Wk + j0 * C_ + c),
                                __ldg(Wq + j1 * C_ + c), __ldg(Wk + j1 * C_ + c));
}

__global__ void prep_wp(const float* __restrict__ Wp) {
    __shared__ float t[32][33];
    int tx = threadIdx.x, ty = threadIdx.y;
    int j0 = blockIdx.y * 32, c0 = blockIdx.x * 32;
    t[ty][tx] = Wp[(j0 + ty) * C_ + c0 + tx];
    __syncthreads();
    g_WpT[(c0 + ty) * C_ + j0 + tx] = t[tx][ty];
}

// ---------------- K1: LIF on raw input -> compacted prescaled-offset lists ----------------
__global__ void __launch_bounds__(256) lif_mask(const float* __restrict__ x) {
    const int s = blockIdx.x, b = blockIdx.y;
    const int c = threadIdx.x, warp = c >> 5, lane = c & 31;
    const int tok = b * 64 + s;

    __shared__ uint32_t smask[T_][8];
    bool spv[T_];

    float v = 0.0f;
    const float* xp = x + (size_t)b * 16384 + (size_t)s * 256 + c;
#pragma unroll
    for (int t = 0; t < T_; t++) {
        float xv = __ldg(xp + (size_t)t * 16777216);
        v += (xv - v) * 0.5f;
        bool sp = (v - 1.0f) >= 0.0f;
        spv[t] = sp;
        if (sp) v = 0.0f;
        uint32_t m = __ballot_sync(0xffffffffu, sp);
        if (lane == 0) smask[t][warp] = m;
    }
    __syncthreads();

    uint32_t* ib = g_off + (size_t)tok * (T_ * IDXSTRIDE);

#pragma unroll
    for (int t = 0; t < T_; t++) {
        uint32_t m = smask[t][warp];
        int base = 0;
#pragma unroll
        for (int w = 0; w < 8; w++)
            if (w < warp) base += __popc(smask[t][w]);
        if (spv[t]) {
            int pos = base + __popc(m & ((1u << lane) - 1u));
            ib[t * IDXSTRIDE + pos] = (uint32_t)(c << 9);   // byte offset of row c
        }
    }

    // pad each list to a multiple of 4 with sentinel row 256 (zeros)
    if (c < T_) {
        int t = c;
        int tot = 0;
#pragma unroll
        for (int w = 0; w < 8; w++) tot += __popc(smask[t][w]);
        int padded = (tot + 3) & ~3;
        for (int p = tot; p < padded; p++) ib[t * IDXSTRIDE + p] = (256u << 9);
    }
    if (c == 0) {
        uint32_t pack = 0;
#pragma unroll
        for (int t = 0; t < T_; t++) {
            int tot = 0;
#pragma unroll
            for (int w = 0; w < 8; w++) tot += __popc(smask[t][w]);
            int ng = (tot + 3) >> 2;            // group count, <= 64 (overflow-safe)
            pack |= (uint32_t)ng << (t * 8);
        }
        g_cnt[tok] = pack;
    }
}

// ---------------- K2: sparse Q/K matvec, 2 heads per CTA, SMEM-resident float4 slice ----------------
extern __shared__ char sWraw[];   // 257*512 = 131584 B (row 256 = zeros)

__global__ void __launch_bounds__(QKTHREADS) qk_kernel(const float* __restrict__ pos) {
    const int p   = blockIdx.x;          // head pair: heads 2p, 2p+1
    const int grp = blockIdx.y;
    const int tid = threadIdx.x, warp = tid >> 5, lane = tid & 31;

    // Stage weights (16B vectors) + zero sentinel row.
    {
        const uint4* src = (const uint4*)(g_Wpack4 + p * 8192);
        uint4* dst = (uint4*)sWraw;
        for (int i = tid; i < 8192; i += QKTHREADS) dst[i] = src[i];
        if (tid < 32) dst[8192 + tid] = make_uint4(0u, 0u, 0u, 0u);
    }
    __syncthreads();

    const int tok0 = (grp * 65536) / NGR;
    const int tok1 = ((grp + 1) * 65536) / NGR;
    const int j0 = p * 64 + lane, j1 = j0 + 32;
    const int h0 = 2 * p;
    const char* laneBase = sWraw + lane * 16;

    for (int i = tok0 + warp; i < tok1; i += (QKTHREADS / 32)) {
        const int b = i >> 6, s = i & 63;
        const uint32_t cpack = __ldg(g_cnt + i);           // warp-uniform
        const uint32_t* ib = g_off + (size_t)i * (T_ * IDXSTRIDE);

        float vq0 = 0.f, vk0 = 0.f, va0 = 0.f;
        float vq1 = 0.f, vk1 = 0.f, va1 = 0.f;
#pragma unroll
        for (int t = 0; t < T_; t++) {
            const int ng = (cpack >> (t * 8)) & 255;

            unsigned long long acc0, acc1;
            {
                float p0 = __ldg(pos + (t * 64 + s) * 256 + j0);
                float p1 = __ldg(pos + (t * 64 + s) * 256 + j1);
                PACK_F32X2(acc0, __float_as_uint(0.0f), __float_as_uint(p0));
                PACK_F32X2(acc1, __float_as_uint(0.0f), __float_as_uint(p1));
            }

            const uint4* gp = (const uint4*)(ib + t * IDXSTRIDE);
            for (int g = 0; g < ng; g++) {
                uint4 w = __ldg(gp + g);                   // 4 prescaled offsets
                {
                    const ulonglong2 wv = *(const ulonglong2*)(laneBase + w.x);
                    ADD_F32X2(acc0, acc0, wv.x);
                    ADD_F32X2(acc1, acc1, wv.y);
                }
                {
                    const ulonglong2 wv = *(const ulonglong2*)(laneBase + w.y);
                    ADD_F32X2(acc0, acc0, wv.x);
                    ADD_F32X2(acc1, acc1, wv.y);
                }
                {
                    const ulonglong2 wv = *(const ulonglong2*)(laneBase + w.z);
                    ADD_F32X2(acc0, acc0, wv.x);
                    ADD_F32X2(acc1, acc1, wv.y);
                }
                {
                    const ulonglong2 wv = *(const ulonglong2*)(laneBase + w.w);
                    ADD_F32X2(acc0, acc0, wv.x);
                    ADD_F32X2(acc1, acc1, wv.y);
                }
            }

            uint32_t aqb0, akb0, aqb1, akb1;
            UNPACK_F32X2(aqb0, akb0, acc0);
            UNPACK_F32X2(aqb1, akb1, acc1);
            float aq0 = __uint_as_float(aqb0), ak0 = __uint_as_float(akb0);
            float aq1 = __uint_as_float(aqb1), ak1 = __uint_as_float(akb1);

            // LIF (exact same arithmetic/order as reference)
            vq0 += (aq0 - vq0) * 0.5f; bool sq0 = (vq0 - 1.f) >= 0.f; if (sq0) vq0 = 0.f;
            vk0 += (ak0 - vk0) * 0.5f; bool sk0 = (vk0 - 1.f) >= 0.f; if (sk0) vk0 = 0.f;
            vq1 += (aq1 - vq1) * 0.5f; bool sq1 = (vq1 - 1.f) >= 0.f; if (sq1) vq1 = 0.f;
            vk1 += (ak1 - vk1) * 0.5f; bool sk1 = (vk1 - 1.f) >= 0.f; if (sk1) vk1 = 0.f;

            uint32_t kb0 = __ballot_sync(0xffffffffu, sk0);
            uint32_t kb1 = __ballot_sync(0xffffffffu, sk1);
            int cq0 = __popc(__ballot_sync(0xffffffffu, sq0));
            int cq1 = __popc(__ballot_sync(0xffffffffu, sq1));
            va0 += ((float)cq0 - va0) * 0.5f; bool sa0 = (va0 - 1.f) >= 0.f; if (sa0) va0 = 0.f;
            va1 += ((float)cq1 - va1) * 0.5f; bool sa1 = (va1 - 1.f) >= 0.f; if (sa1) va1 = 0.f;

            if (lane == 0) {
                size_t kbase = (((size_t)t * B_ + b) * S_ + s) * 8;
                g_kbits[kbase + h0]     = kb0;
                g_kbits[kbase + h0 + 1] = kb1;
                size_t abase = ((size_t)t * B_ + b) * 8;
                g_att[(abase + h0) * 64 + s]     = sa0 ? 1u : 0u;
                g_att[(abase + h0 + 1) * 64 + s] = sa1 ? 1u : 0u;
            }
        }
    }
}

// ---------------- K3: gather x2 bits, sparse Wp matvec + bias, write y (+ zero attn_out) ----------------
__global__ void __launch_bounds__(256) kernelB(const float* __restrict__ bp,
                                               float* __restrict__ out, int write_zero) {
    const int s = blockIdx.x;
    const int b = blockIdx.y;
    const int j = threadIdx.x;
    const int h = j >> 5, d = j & 31;
    const int wh = s >> 3, ww = s & 7;

    const int t_k = b >> 8;
    const int b_k = (b & 255) * 4 + (h >> 1);

    __shared__ uint32_t x2m[T_][8];

#pragma unroll
    for (int t = 0; t < T_; t++) {
        int s_k = ((h & 1) << 5) + t * 8 + wh;
        uint32_t kw = g_kbits[(((size_t)t_k * B_ + b_k) * S_ + s_k) * 8 + ww];
        uint8_t ab = g_att[(((size_t)t_k * B_ + b_k) * 8 + ((h & 1) * 4 + t)) * S_ + s];
        bool x2 = (((kw >> d) & 1u) != 0u) && (ab != 0u);
        uint32_t m = __ballot_sync(0xffffffffu, x2);
        if (d == 0) x2m[t][h] = m;
    }
    __syncthreads();

    const float bias = __ldg(bp + j);
#pragma unroll
    for (int t = 0; t < T_; t++) {
        float acc = bias;
#pragma unroll
        for (int w = 0; w < 8; w++) {
            uint32_t m = x2m[t][w];
            while (m) {
                int c = (w << 5) + __ffs(m) - 1;
                m &= m - 1;
                acc += g_WpT[c * C_ + j];
            }
        }
        size_t off = (((size_t)t * B_ + b) * S_ + s) * 256 + j;
        out[off] = acc;
        // attn_out = lif(x2) is identically zero: x2 in {0,1}, v <- (v+x)/2 < 1 always.
        if (write_zero) out[Y_ELEMS + off] = 0.0f;
    }
}

__global__ void zfill_tail(float* __restrict__ p, size_t n) {
    size_t i = (size_t)blockIdx.x * blockDim.x + threadIdx.x;
    if (i < n) p[i] = 0.f;
}

extern "C" void kernel_launch(void* const* d_in, const int* in_sizes, int n_in,
                              void* d_out, int out_size) {
    const float* x   = (const float*)d_in[0];
    const float* Wq  = (const float*)d_in[1];
    const float* Wk  = (const float*)d_in[2];
    const float* Wp  = (const float*)d_in[3];
    const float* bp  = (const float*)d_in[4];
    const float* pos = (const float*)d_in[5];
    float* out = (float*)d_out;

    cudaFuncSetAttribute(qk_kernel, cudaFuncAttributeMaxDynamicSharedMemorySize, 131584);

    prep_pack<<<128, 256>>>(Wq, Wk);
    prep_wp<<<dim3(8, 8), dim3(32, 32)>>>(Wp);
    lif_mask<<<dim3(64, 1024), 256>>>(x);
    qk_kernel<<<dim3(NPAIR, NGR), QKTHREADS, 131584>>>(pos);

    int write_zero = ((long long)out_size >= 2 * Y_ELEMS) ? 1 : 0;
    kernelB<<<dim3(64, 1024), 256>>>(bp, out, write_zero);

    long long extra = (long long)out_size - (write_zero ? 2 * Y_ELEMS : Y_ELEMS);
    if (extra > 0) {
        long long base = write_zero ? 2 * Y_ELEMS : Y_ELEMS;
        int blocks = (int)((extra + 255) / 256);
        zfill_tail<<<blocks, 256>>>(out + base, (size_t)extra);
    }
}